// round 1
// baseline (speedup 1.0000x reference)
#include <cuda_runtime.h>

#define Bsz 64
#define Tn  16384
#define H1n 64
#define H2n 8

typedef unsigned long long u64;

__device__ __forceinline__ u64 pk2(float lo, float hi) {
    u64 r; asm("mov.b64 %0, {%1,%2};" : "=l"(r) : "f"(lo), "f"(hi)); return r;
}
__device__ __forceinline__ float2 upk2(u64 v) {
    float2 f; asm("mov.b64 {%0,%1}, %2;" : "=f"(f.x), "=f"(f.y) : "l"(v)); return f;
}
// packed 2-wide fp32 FMA (Blackwell f32x2 pipe) : d = a*b + d
__device__ __forceinline__ void fma2(u64 &d, u64 a, u64 b) {
    asm("fma.rn.f32x2 %0, %1, %2, %0;" : "+l"(d) : "l"(a), "l"(b));
}
__device__ __forceinline__ void add2(u64 &d, u64 a) {
    asm("add.rn.f32x2 %0, %0, %1;" : "+l"(d) : "l"(a));
}

__device__ __forceinline__ float sigm(float v) {
    return __fdividef(1.0f, 1.0f + __expf(-v));
}
__device__ __forceinline__ float tanh_(float v) {
    return __fdividef(2.0f, 1.0f + __expf(-2.0f * v)) - 1.0f;
}

// One block per batch row. 9 warps:
//   warps 0-7 : layer-1. lane = (cell%8)*4 + gate, warp w owns cells [8w, 8w+8).
//               gate rows in weight matrices: row = gate*64 + cell  (i,f,g,o order).
//               cell update done with intra-warp shuffles (no block barrier).
//   warp 8    : layer-2 + output, software-pipelined one step behind layer-1
//               (both stages only consume h1[t-1], held in a double buffer).
// One __syncthreads per timestep.
__global__ void __launch_bounds__(288, 1) lstm2_kernel(
    const float* __restrict__ x,
    const float* __restrict__ Wih1,
    const float* __restrict__ Whh1,
    const float* __restrict__ b1,
    const float* __restrict__ Wih2,
    const float* __restrict__ Whh2,
    const float* __restrict__ b2,
    const float* __restrict__ Wout,
    const float* __restrict__ bout,
    float* __restrict__ out)
{
    const int b    = blockIdx.x;
    const int tid  = threadIdx.x;
    const int wid  = tid >> 5;
    const int lane = tid & 31;

    __shared__ __align__(16) float h1buf[2][H1n];

    const float* xb = x + (size_t)b * Tn;
    float*       yb = out + (size_t)b * Tn;

    // persistent per-thread state
    u64   w[32];                       // packed weight row (64 floats)
    float wih = 0.f, bias = 0.f;
    float c1 = 0.f, h1v = 0.f;
    float w2h[8];                      // layer-2 recurrent weights (warp 8)
    float bias2 = 0.f, woutv = 0.f, boutv = 0.f;
    float c2 = 0.f, h2v = 0.f;
    int   cell, q;

    if (wid < 8) {
        cell = wid * 8 + (lane >> 2);
        q    = lane & 3;
        const int row = q * H1n + cell;
        const float2* wp = (const float2*)(Whh1 + row * H1n);
        #pragma unroll
        for (int k = 0; k < 32; k++) { float2 f = wp[k]; w[k] = pk2(f.x, f.y); }
        wih  = Wih1[row];
        bias = b1[row];
        if (tid < H1n) h1buf[0][tid] = 0.0f;
        #pragma unroll
        for (int k = 0; k < 8; k++) w2h[k] = 0.f;
    } else {
        cell = lane >> 2;
        q    = lane & 3;
        const int row = q * H2n + cell;
        const float2* wp = (const float2*)(Wih2 + row * H1n);
        #pragma unroll
        for (int k = 0; k < 32; k++) { float2 f = wp[k]; w[k] = pk2(f.x, f.y); }
        #pragma unroll
        for (int k = 0; k < 8; k++) w2h[k] = Whh2[row * H2n + k];
        bias2 = b2[row];
        woutv = Wout[cell];
        boutv = bout[0];
    }
    __syncthreads();

    float x_cur = xb[0];
    int p = 0;

    for (int t = 0; t <= Tn; ++t) {
        if (wid < 8) {
            if (t < Tn) {
                float x_nxt = (t + 1 < Tn) ? xb[t + 1] : 0.0f;
                u64 a0 = pk2(fmaf(x_cur, wih, bias), 0.0f);
                u64 a1 = pk2(0.f, 0.f), a2 = a1, a3 = a1;
                const ulonglong2* hp = (const ulonglong2*)(&h1buf[p][0]);
                #pragma unroll
                for (int k = 0; k < 8; k++) {
                    ulonglong2 ha = hp[2 * k];
                    ulonglong2 hb = hp[2 * k + 1];
                    fma2(a0, w[4 * k + 0], ha.x);
                    fma2(a1, w[4 * k + 1], ha.y);
                    fma2(a2, w[4 * k + 2], hb.x);
                    fma2(a3, w[4 * k + 3], hb.y);
                }
                add2(a0, a1); add2(a2, a3); add2(a0, a2);
                float2 s2 = upk2(a0);
                float g = s2.x + s2.y;
                float act = (q == 2) ? tanh_(g) : sigm(g);
                const unsigned bl = lane & ~3u;
                float ai = __shfl_sync(0xffffffffu, act, bl + 0);
                float af = __shfl_sync(0xffffffffu, act, bl + 1);
                float ag = __shfl_sync(0xffffffffu, act, bl + 2);
                float ao = __shfl_sync(0xffffffffu, act, bl + 3);
                c1  = fmaf(af, c1, ai * ag);
                h1v = ao * tanh_(c1);
                if (q == 0) h1buf[p ^ 1][cell] = h1v;
                x_cur = x_nxt;
            }
        } else {
            if (t >= 1) {
                const int s = t - 1;
                u64 a0 = pk2(bias2, 0.0f);
                u64 a1 = pk2(0.f, 0.f), a2 = a1, a3 = a1;
                const ulonglong2* hp = (const ulonglong2*)(&h1buf[p][0]);
                #pragma unroll
                for (int k = 0; k < 8; k++) {
                    ulonglong2 ha = hp[2 * k];
                    ulonglong2 hb = hp[2 * k + 1];
                    fma2(a0, w[4 * k + 0], ha.x);
                    fma2(a1, w[4 * k + 1], ha.y);
                    fma2(a2, w[4 * k + 2], hb.x);
                    fma2(a3, w[4 * k + 3], hb.y);
                }
                add2(a0, a1); add2(a2, a3); add2(a0, a2);
                float2 s2 = upk2(a0);
                float g = s2.x + s2.y;
                #pragma unroll
                for (int k = 0; k < 8; k++) {
                    float hk = __shfl_sync(0xffffffffu, h2v, 4 * k);
                    g = fmaf(w2h[k], hk, g);
                }
                float act = (q == 2) ? tanh_(g) : sigm(g);
                const unsigned bl = lane & ~3u;
                float ai = __shfl_sync(0xffffffffu, act, bl + 0);
                float af = __shfl_sync(0xffffffffu, act, bl + 1);
                float ag = __shfl_sync(0xffffffffu, act, bl + 2);
                float ao = __shfl_sync(0xffffffffu, act, bl + 3);
                c2  = fmaf(af, c2, ai * ag);
                h2v = ao * tanh_(c2);
                float contrib = (q == 0) ? h2v * woutv : 0.0f;
                #pragma unroll
                for (int off = 16; off >= 1; off >>= 1)
                    contrib += __shfl_xor_sync(0xffffffffu, contrib, off);
                if (lane == 0) yb[s] = contrib + boutv + xb[s];
            }
        }
        __syncthreads();
        p ^= 1;
    }

    // final states: layout  y | h1 | c1 | h2 | c2  (each with leading dim 1)
    const int OH1 = Bsz * Tn;
    const int OC1 = OH1 + Bsz * H1n;
    const int OH2 = OC1 + Bsz * H1n;
    const int OC2 = OH2 + Bsz * H2n;
    if (wid < 8) {
        if (q == 0) {
            out[OH1 + b * H1n + cell] = h1v;
            out[OC1 + b * H1n + cell] = c1;
        }
    } else {
        if (q == 0) {
            out[OH2 + b * H2n + cell] = h2v;
            out[OC2 + b * H2n + cell] = c2;
        }
    }
}

extern "C" void kernel_launch(void* const* d_in, const int* in_sizes, int n_in,
                              void* d_out, int out_size) {
    const float* x     = (const float*)d_in[0];
    const float* Wih1  = (const float*)d_in[1];
    const float* Whh1  = (const float*)d_in[2];
    const float* b1    = (const float*)d_in[3];
    const float* Wih2  = (const float*)d_in[4];
    const float* Whh2  = (const float*)d_in[5];
    const float* b2    = (const float*)d_in[6];
    const float* Wout  = (const float*)d_in[7];
    const float* bout  = (const float*)d_in[8];
    float* out = (float*)d_out;

    lstm2_kernel<<<Bsz, 288>>>(x, Wih1, Whh1, b1, Wih2, Whh2, b2, Wout, bout, out);
}

// round 2
// speedup vs baseline: 1.2546x; 1.2546x over previous
#include <cuda_runtime.h>

#define Bsz 64
#define Tn  16384
#define H1n 64
#define H2n 8

typedef unsigned long long u64;

__device__ __forceinline__ u64 pk2(float lo, float hi) {
    u64 r; asm("mov.b64 %0, {%1,%2};" : "=l"(r) : "f"(lo), "f"(hi)); return r;
}
__device__ __forceinline__ float2 upk2(u64 v) {
    float2 f; asm("mov.b64 {%0,%1}, %2;" : "=f"(f.x), "=f"(f.y) : "l"(v)); return f;
}
// packed 2-wide fp32 FMA (Blackwell f32x2 pipe) : d = a*b + d
__device__ __forceinline__ void fma2(u64 &d, u64 a, u64 b) {
    asm("fma.rn.f32x2 %0, %1, %2, %0;" : "+l"(d) : "l"(a), "l"(b));
}
__device__ __forceinline__ void add2(u64 &d, u64 a) {
    asm("add.rn.f32x2 %0, %0, %1;" : "+l"(d) : "l"(a));
}

// HW tanh (MUFU.TANH): 1 MUFU, lat ~16  vs ~48 for the expf/rcp chain
__device__ __forceinline__ float tanh_(float v) {
    float r; asm("tanh.approx.f32 %0, %1;" : "=f"(r) : "f"(v)); return r;
}
__device__ __forceinline__ float sigm(float v) {
    return fmaf(0.5f, tanh_(0.5f * v), 0.5f);
}

// One block per batch row. 9 warps:
//   warps 0-7 : layer-1. lane = (cell%8)*4 + gate, warp w owns cells [8w, 8w+8).
//               gate rows in weight matrices: row = gate*64 + cell  (i,f,g,o order).
//   warp 8    : layer-2 + output, software-pipelined one step behind layer-1
//               (consumes h1[t-1] from a double buffer).
// One __syncthreads per timestep.
__global__ void __launch_bounds__(288, 1) lstm2_kernel(
    const float* __restrict__ x,
    const float* __restrict__ Wih1,
    const float* __restrict__ Whh1,
    const float* __restrict__ b1,
    const float* __restrict__ Wih2,
    const float* __restrict__ Whh2,
    const float* __restrict__ b2,
    const float* __restrict__ Wout,
    const float* __restrict__ bout,
    float* __restrict__ out)
{
    const int b    = blockIdx.x;
    const int tid  = threadIdx.x;
    const int wid  = tid >> 5;
    const int lane = tid & 31;

    __shared__ __align__(16) float h1buf[2][H1n];

    const float* xb = x + (size_t)b * Tn;
    float*       yb = out + (size_t)b * Tn;

    // persistent per-thread state
    u64   w[32];                       // packed weight row (64 floats)
    float wih = 0.f, bias = 0.f;
    float c1 = 0.f, h1v = 0.f;
    float w2h[8];                      // layer-2 recurrent weights (warp 8)
    float bias2 = 0.f, woutv = 0.f, boutv = 0.f;
    float c2 = 0.f, h2v = 0.f;
    int   cell, q;

    if (wid < 8) {
        cell = wid * 8 + (lane >> 2);
        q    = lane & 3;
        const int row = q * H1n + cell;
        const float2* wp = (const float2*)(Whh1 + row * H1n);
        #pragma unroll
        for (int k = 0; k < 32; k++) { float2 f = wp[k]; w[k] = pk2(f.x, f.y); }
        wih  = Wih1[row];
        bias = b1[row];
        if (tid < H1n) h1buf[0][tid] = 0.0f;
        #pragma unroll
        for (int k = 0; k < 8; k++) w2h[k] = 0.f;
    } else {
        cell = lane >> 2;
        q    = lane & 3;
        const int row = q * H2n + cell;
        const float2* wp = (const float2*)(Wih2 + row * H1n);
        #pragma unroll
        for (int k = 0; k < 32; k++) { float2 f = wp[k]; w[k] = pk2(f.x, f.y); }
        #pragma unroll
        for (int k = 0; k < 8; k++) w2h[k] = Whh2[row * H2n + k];
        bias2 = b2[row];
        woutv = Wout[cell];
        boutv = bout[0];
    }
    __syncthreads();

    // depth-2 x prefetch (covers the every-32-step cache-line miss)
    float x_cur = xb[0];
    float x_n1  = xb[1];
    int p = 0;

    for (int t = 0; t <= Tn; ++t) {
        if (wid < 8) {
            if (t < Tn) {
                float x_n2 = (t + 2 < Tn) ? xb[t + 2] : 0.0f;
                u64 a0 = pk2(fmaf(x_cur, wih, bias), 0.0f);
                u64 a1 = pk2(0.f, 0.f), a2 = a1, a3 = a1;
                const ulonglong2* hp = (const ulonglong2*)(&h1buf[p][0]);
                #pragma unroll
                for (int k = 0; k < 8; k++) {
                    ulonglong2 ha = hp[2 * k];
                    ulonglong2 hb = hp[2 * k + 1];
                    fma2(a0, w[4 * k + 0], ha.x);
                    fma2(a1, w[4 * k + 1], ha.y);
                    fma2(a2, w[4 * k + 2], hb.x);
                    fma2(a3, w[4 * k + 3], hb.y);
                }
                add2(a0, a1); add2(a2, a3); add2(a0, a2);
                float2 s2 = upk2(a0);
                float g = s2.x + s2.y;
                float act = (q == 2) ? tanh_(g) : sigm(g);
                const unsigned bl = lane & ~3u;
                float ai = __shfl_sync(0xffffffffu, act, bl + 0);
                float af = __shfl_sync(0xffffffffu, act, bl + 1);
                float ag = __shfl_sync(0xffffffffu, act, bl + 2);
                float ao = __shfl_sync(0xffffffffu, act, bl + 3);
                c1  = fmaf(af, c1, ai * ag);
                h1v = ao * tanh_(c1);
                if (q == 0) h1buf[p ^ 1][cell] = h1v;
                x_cur = x_n1;
                x_n1  = x_n2;
            }
        } else {
            if (t >= 1) {
                const int s = t - 1;
                u64 a0 = pk2(bias2, 0.0f);
                u64 a1 = pk2(0.f, 0.f), a2 = a1, a3 = a1;
                const ulonglong2* hp = (const ulonglong2*)(&h1buf[p][0]);
                #pragma unroll
                for (int k = 0; k < 8; k++) {
                    ulonglong2 ha = hp[2 * k];
                    ulonglong2 hb = hp[2 * k + 1];
                    fma2(a0, w[4 * k + 0], ha.x);
                    fma2(a1, w[4 * k + 1], ha.y);
                    fma2(a2, w[4 * k + 2], hb.x);
                    fma2(a3, w[4 * k + 3], hb.y);
                }
                add2(a0, a1); add2(a2, a3); add2(a0, a2);
                float2 s2 = upk2(a0);
                float g = s2.x + s2.y;
                // h2 recurrence: 8 gathers, 2 fma accumulators (serial depth 4)
                float r0 = 0.f, r1 = 0.f;
                #pragma unroll
                for (int k = 0; k < 4; k++) {
                    float hk0 = __shfl_sync(0xffffffffu, h2v, 8 * k);
                    float hk1 = __shfl_sync(0xffffffffu, h2v, 8 * k + 4);
                    r0 = fmaf(w2h[2 * k],     hk0, r0);
                    r1 = fmaf(w2h[2 * k + 1], hk1, r1);
                }
                g += r0 + r1;
                float act = (q == 2) ? tanh_(g) : sigm(g);
                const unsigned bl = lane & ~3u;
                float ai = __shfl_sync(0xffffffffu, act, bl + 0);
                float af = __shfl_sync(0xffffffffu, act, bl + 1);
                float ag = __shfl_sync(0xffffffffu, act, bl + 2);
                float ao = __shfl_sync(0xffffffffu, act, bl + 3);
                c2  = fmaf(af, c2, ai * ag);
                h2v = ao * tanh_(c2);
                // output dot: h2v is replicated across the 4 gate-lanes of each
                // cell; butterfly over the 3 cell bits (offsets 4/8/16) sums all
                // 8 cells exactly once. 3 SHFLs instead of 5.
                float prod = h2v * woutv;
                prod += __shfl_xor_sync(0xffffffffu, prod, 4);
                prod += __shfl_xor_sync(0xffffffffu, prod, 8);
                prod += __shfl_xor_sync(0xffffffffu, prod, 16);
                if (lane == 0) yb[s] = prod + boutv + xb[s];
            }
        }
        __syncthreads();
        p ^= 1;
    }

    // final states: layout  y | h1 | c1 | h2 | c2  (each with leading dim 1)
    const int OH1 = Bsz * Tn;
    const int OC1 = OH1 + Bsz * H1n;
    const int OH2 = OC1 + Bsz * H1n;
    const int OC2 = OH2 + Bsz * H2n;
    if (wid < 8) {
        if (q == 0) {
            out[OH1 + b * H1n + cell] = h1v;
            out[OC1 + b * H1n + cell] = c1;
        }
    } else {
        if (q == 0) {
            out[OH2 + b * H2n + cell] = h2v;
            out[OC2 + b * H2n + cell] = c2;
        }
    }
}

extern "C" void kernel_launch(void* const* d_in, const int* in_sizes, int n_in,
                              void* d_out, int out_size) {
    const float* x     = (const float*)d_in[0];
    const float* Wih1  = (const float*)d_in[1];
    const float* Whh1  = (const float*)d_in[2];
    const float* b1    = (const float*)d_in[3];
    const float* Wih2  = (const float*)d_in[4];
    const float* Whh2  = (const float*)d_in[5];
    const float* b2    = (const float*)d_in[6];
    const float* Wout  = (const float*)d_in[7];
    const float* bout  = (const float*)d_in[8];
    float* out = (float*)d_out;

    lstm2_kernel<<<Bsz, 288>>>(x, Wih1, Whh1, b1, Wih2, Whh2, b2, Wout, bout, out);
}

// round 3
// speedup vs baseline: 1.3373x; 1.0659x over previous
#include <cuda_runtime.h>

#define Bsz 64
#define Tn  16384
#define H1n 64
#define H2n 8
#define RING 64
#define RSTR 9   // ring row stride (9 floats) -> conflict-free LDS across lanes

typedef unsigned long long u64;

__device__ __forceinline__ u64 pk2(float lo, float hi) {
    u64 r; asm("mov.b64 %0, {%1,%2};" : "=l"(r) : "f"(lo), "f"(hi)); return r;
}
__device__ __forceinline__ float2 upk2(u64 v) {
    float2 f; asm("mov.b64 {%0,%1}, %2;" : "=f"(f.x), "=f"(f.y) : "l"(v)); return f;
}
__device__ __forceinline__ void fma2(u64 &d, u64 a, u64 b) {
    asm("fma.rn.f32x2 %0, %1, %2, %0;" : "+l"(d) : "l"(a), "l"(b));
}
__device__ __forceinline__ void add2(u64 &d, u64 a) {
    asm("add.rn.f32x2 %0, %0, %1;" : "+l"(d) : "l"(a));
}
__device__ __forceinline__ float tanh_(float v) {
    float r; asm("tanh.approx.f32 %0, %1;" : "=f"(r) : "f"(v)); return r;
}
__device__ __forceinline__ float sigm(float v) {
    return fmaf(0.5f, tanh_(0.5f * v), 0.5f);
}

// One block per batch row. 10 warps:
//   warps 0-7 : layer-1 (lane = cell*4+gate within warp's 8 cells).
//   warp 8    : layer-2 state only (h2,c2), one step behind layer-1; writes h2
//               into a smem ring. NO output projection on this chain.
//   warp 9    : output projection, batched: every 32 steps computes 32 y values
//               from the h2 ring (coalesced x load / y store). Fully off-path.
__global__ void __launch_bounds__(320, 1) lstm2_kernel(
    const float* __restrict__ x,
    const float* __restrict__ Wih1,
    const float* __restrict__ Whh1,
    const float* __restrict__ b1,
    const float* __restrict__ Wih2,
    const float* __restrict__ Whh2,
    const float* __restrict__ b2,
    const float* __restrict__ Wout,
    const float* __restrict__ bout,
    float* __restrict__ out)
{
    const int b    = blockIdx.x;
    const int tid  = threadIdx.x;
    const int wid  = tid >> 5;
    const int lane = tid & 31;

    __shared__ __align__(16) float h1buf[2][H1n];
    __shared__ float h2ring[RING * RSTR];

    const float* xb = x + (size_t)b * Tn;
    float*       yb = out + (size_t)b * Tn;

    u64   w[32];
    float wih = 0.f, bias = 0.f;
    float c1 = 0.f, h1v = 0.f;
    float w2h[8];
    float bias2 = 0.f, woutv = 0.f, boutv = 0.f;
    float c2 = 0.f, h2v = 0.f;
    int   cell = 0, q = 0;

    if (wid < 8) {
        cell = wid * 8 + (lane >> 2);
        q    = lane & 3;
        const int row = q * H1n + cell;
        const float2* wp = (const float2*)(Whh1 + row * H1n);
        #pragma unroll
        for (int k = 0; k < 32; k++) { float2 f = wp[k]; w[k] = pk2(f.x, f.y); }
        wih  = Wih1[row];
        bias = b1[row];
        if (tid < H1n) h1buf[0][tid] = 0.0f;
    } else if (wid == 8) {
        cell = lane >> 2;
        q    = lane & 3;
        const int row = q * H2n + cell;
        const float2* wp = (const float2*)(Wih2 + row * H1n);
        #pragma unroll
        for (int k = 0; k < 32; k++) { float2 f = wp[k]; w[k] = pk2(f.x, f.y); }
        #pragma unroll
        for (int k = 0; k < 8; k++) w2h[k] = Whh2[row * H2n + k];
        bias2 = b2[row];
        woutv = Wout[cell];
        boutv = bout[0];
    } else { // wid == 9 : output-projection warp
        #pragma unroll
        for (int k = 0; k < 8; k++) w2h[k] = Wout[k];
        boutv = bout[0];
    }
    __syncthreads();

    float x_cur = xb[0];
    float x_n1  = xb[1];
    int p = 0;

    for (int t = 0; t <= Tn; ++t) {
        if (wid < 8) {
            if (t < Tn) {
                float x_n2 = (t + 2 < Tn) ? xb[t + 2] : 0.0f;
                u64 a0 = pk2(fmaf(x_cur, wih, bias), 0.0f);
                u64 a1 = pk2(0.f, 0.f), a2 = a1, a3 = a1;
                const ulonglong2* hp = (const ulonglong2*)(&h1buf[p][0]);
                #pragma unroll
                for (int k = 0; k < 8; k++) {
                    ulonglong2 ha = hp[2 * k];
                    ulonglong2 hb = hp[2 * k + 1];
                    fma2(a0, w[4 * k + 0], ha.x);
                    fma2(a1, w[4 * k + 1], ha.y);
                    fma2(a2, w[4 * k + 2], hb.x);
                    fma2(a3, w[4 * k + 3], hb.y);
                }
                add2(a0, a1); add2(a2, a3); add2(a0, a2);
                float2 s2 = upk2(a0);
                float g = s2.x + s2.y;
                float act = (q == 2) ? tanh_(g) : sigm(g);
                const unsigned bl = lane & ~3u;
                float ai = __shfl_sync(0xffffffffu, act, bl + 0);
                float af = __shfl_sync(0xffffffffu, act, bl + 1);
                float ag = __shfl_sync(0xffffffffu, act, bl + 2);
                float ao = __shfl_sync(0xffffffffu, act, bl + 3);
                c1  = fmaf(af, c1, ai * ag);
                h1v = ao * tanh_(c1);
                if (q == 0) h1buf[p ^ 1][cell] = h1v;
                x_cur = x_n1;
                x_n1  = x_n2;
            }
        } else if (wid == 8) {
            if (t >= 1) {
                const int s = t - 1;
                u64 a0 = pk2(bias2, 0.0f);
                u64 a1 = pk2(0.f, 0.f), a2 = a1, a3 = a1;
                const ulonglong2* hp = (const ulonglong2*)(&h1buf[p][0]);
                #pragma unroll
                for (int k = 0; k < 8; k++) {
                    ulonglong2 ha = hp[2 * k];
                    ulonglong2 hb = hp[2 * k + 1];
                    fma2(a0, w[4 * k + 0], ha.x);
                    fma2(a1, w[4 * k + 1], ha.y);
                    fma2(a2, w[4 * k + 2], hb.x);
                    fma2(a3, w[4 * k + 3], hb.y);
                }
                add2(a0, a1); add2(a2, a3); add2(a0, a2);
                float2 s2 = upk2(a0);
                float g = s2.x + s2.y;
                // h2 recurrence: 8 gathers, 4 fma accumulators (serial depth 2)
                float r0, r1, r2, r3;
                {
                    float h0 = __shfl_sync(0xffffffffu, h2v, 0);
                    float h1_ = __shfl_sync(0xffffffffu, h2v, 4);
                    float h2_ = __shfl_sync(0xffffffffu, h2v, 8);
                    float h3 = __shfl_sync(0xffffffffu, h2v, 12);
                    float h4 = __shfl_sync(0xffffffffu, h2v, 16);
                    float h5 = __shfl_sync(0xffffffffu, h2v, 20);
                    float h6 = __shfl_sync(0xffffffffu, h2v, 24);
                    float h7 = __shfl_sync(0xffffffffu, h2v, 28);
                    r0 = w2h[0] * h0; r1 = w2h[1] * h1_;
                    r2 = w2h[2] * h2_; r3 = w2h[3] * h3;
                    r0 = fmaf(w2h[4], h4, r0); r1 = fmaf(w2h[5], h5, r1);
                    r2 = fmaf(w2h[6], h6, r2); r3 = fmaf(w2h[7], h7, r3);
                }
                g += (r0 + r1) + (r2 + r3);
                float act = (q == 2) ? tanh_(g) : sigm(g);
                const unsigned bl = lane & ~3u;
                float ai = __shfl_sync(0xffffffffu, act, bl + 0);
                float af = __shfl_sync(0xffffffffu, act, bl + 1);
                float ag = __shfl_sync(0xffffffffu, act, bl + 2);
                float ao = __shfl_sync(0xffffffffu, act, bl + 3);
                c2  = fmaf(af, c2, ai * ag);
                h2v = ao * tanh_(c2);
                if (q == 0) h2ring[(s & (RING - 1)) * RSTR + cell] = h2v;
            }
        } else { // wid == 9 : batched output projection
            if (t >= 32 && (t & 31) == 0) {
                const int s = t - 33 + lane;     // steps [t-33, t-2]
                if (s >= 0) {
                    const float* r = &h2ring[(s & (RING - 1)) * RSTR];
                    float acc0 = boutv, acc1 = 0.f;
                    #pragma unroll
                    for (int k = 0; k < 4; k++) {
                        acc0 = fmaf(r[2 * k],     w2h[2 * k],     acc0);
                        acc1 = fmaf(r[2 * k + 1], w2h[2 * k + 1], acc1);
                    }
                    yb[s] = acc0 + acc1 + xb[s];
                }
            }
        }
        __syncthreads();
        p ^= 1;
    }

    // last y (step Tn-1): warp 8 still holds h2v for it
    if (wid == 8) {
        float prod = h2v * woutv;
        prod += __shfl_xor_sync(0xffffffffu, prod, 4);
        prod += __shfl_xor_sync(0xffffffffu, prod, 8);
        prod += __shfl_xor_sync(0xffffffffu, prod, 16);
        if (lane == 0) yb[Tn - 1] = prod + boutv + xb[Tn - 1];
    }

    // final states: layout  y | h1 | c1 | h2 | c2  (each with leading dim 1)
    const int OH1 = Bsz * Tn;
    const int OC1 = OH1 + Bsz * H1n;
    const int OH2 = OC1 + Bsz * H1n;
    const int OC2 = OH2 + Bsz * H2n;
    if (wid < 8) {
        if (q == 0) {
            out[OH1 + b * H1n + cell] = h1v;
            out[OC1 + b * H1n + cell] = c1;
        }
    } else if (wid == 8) {
        if (q == 0) {
            out[OH2 + b * H2n + cell] = h2v;
            out[OC2 + b * H2n + cell] = c2;
        }
    }
}

extern "C" void kernel_launch(void* const* d_in, const int* in_sizes, int n_in,
                              void* d_out, int out_size) {
    const float* x     = (const float*)d_in[0];
    const float* Wih1  = (const float*)d_in[1];
    const float* Whh1  = (const float*)d_in[2];
    const float* b1    = (const float*)d_in[3];
    const float* Wih2  = (const float*)d_in[4];
    const float* Whh2  = (const float*)d_in[5];
    const float* b2    = (const float*)d_in[6];
    const float* Wout  = (const float*)d_in[7];
    const float* bout  = (const float*)d_in[8];
    float* out = (float*)d_out;

    lstm2_kernel<<<Bsz, 320>>>(x, Wih1, Whh1, b1, Wih2, Whh2, b2, Wout, bout, out);
}